// round 14
// baseline (speedup 1.0000x reference)
#include <cuda_runtime.h>
#include <cuda_fp16.h>
#include <cstdint>

// Problem constants
#define INC   32
#define INN   50000
#define OUTC  32
#define OUTN  8192
#define MAXD  16
#define NBATCH 8
#define NC    (NBATCH * INC)   // 256
#define TI    256

// W-transformed table z[i][n*32+d] = sum_c x[n][c][i] * W[c][d], fp16 (25.6 MB)
__device__ __align__(16) __half g_z[(size_t)INN * NC];

// ---- packed f32x2 helpers (2x fp32 FMA rate; PTX-only per sm_103a) ----
__device__ __forceinline__ unsigned long long pack2(float a, float b) {
    unsigned long long r;
    asm("mov.b64 %0, {%1, %2};" : "=l"(r) : "f"(a), "f"(b));
    return r;
}
__device__ __forceinline__ void unpack2(unsigned long long v, float& a, float& b) {
    asm("mov.b64 {%0, %1}, %2;" : "=f"(a), "=f"(b) : "l"(v));
}
__device__ __forceinline__ void fma2(unsigned long long& d,
                                     unsigned long long a, unsigned long long b) {
    asm("fma.rn.f32x2 %0, %1, %2, %0;" : "+l"(d) : "l"(a), "l"(b));
}

// ---------------------------------------------------------------------------
// Kernel 1: transform+transpose.
//   z[i][n*32+d] = sum_c x[n][c][i] * W[c][d]   (fp32 math, fp16 store)
// Block: n = blockIdx.y, i-tile of TI=256. 256 threads.
// ---------------------------------------------------------------------------
__global__ __launch_bounds__(256) void xform_kernel(
    const float* __restrict__ x,       // [NBATCH][INC][INN]
    const float* __restrict__ weight)  // [INC][OUTC]
{
    __shared__ float tile[32][260];                       // 33.3 KB
    __shared__ __align__(16) float s_wd[INC * OUTC * 2];  // duplicated pairs, 8 KB

    const int tid = threadIdx.x;
    const int n   = blockIdx.y;
    const int i0  = blockIdx.x * TI;

    // duplicated weight table for f32x2 b-operand
    for (int k = tid; k < INC * OUTC; k += 256) {
        const float w = weight[k];
        s_wd[2 * k + 0] = w;
        s_wd[2 * k + 1] = w;
    }

    // load x tile: warp = 4 c-rows x 8 quads (128B contiguous per row)
    {
        const int c_l  = tid >> 3;               // 0..31
        const int iq_b = tid & 7;
        const float* xrow = x + (size_t)(n * INC + c_l) * INN;
        #pragma unroll
        for (int r = 0; r < 8; r++) {
            const int iq = iq_b + 8 * r;         // 0..63
            const int i  = i0 + 4 * iq;
            float4 v = make_float4(0.f, 0.f, 0.f, 0.f);
            if (i < INN) v = *reinterpret_cast<const float4*>(xrow + i); // INN%4==0
            *reinterpret_cast<float4*>(&tile[c_l][4 * iq]) = v;
        }
    }
    __syncthreads();

    // compute: 4 i x 8 d per thread, f32x2 over i-pairs
    const int dg  = tid & 3;                     // d in [8dg, 8dg+8)
    const int iq4 = tid >> 2;                    // i in [4iq4, 4iq4+4)

    unsigned long long acc[16];                  // [d][pair]
    #pragma unroll
    for (int k = 0; k < 16; k++) acc[k] = 0ull;  // two +0.0f

    #pragma unroll
    for (int c = 0; c < 32; c++) {
        const float4 t = *reinterpret_cast<const float4*>(&tile[c][4 * iq4]);
        const unsigned long long t01 = pack2(t.x, t.y);
        const unsigned long long t23 = pack2(t.z, t.w);
        const unsigned long long* wrow = reinterpret_cast<const unsigned long long*>(
            s_wd + 2 * (c * OUTC + 8 * dg));
        #pragma unroll
        for (int d = 0; d < 8; d++) {
            const unsigned long long w2 = wrow[d];
            fma2(acc[2 * d + 0], t01, w2);
            fma2(acc[2 * d + 1], t23, w2);
        }
    }

    // store z from registers: per local-i, 8 d-halves = one uint4
    #pragma unroll
    for (int p = 0; p < 2; p++) {
        float e0[8], e1[8];
        #pragma unroll
        for (int d = 0; d < 8; d++) unpack2(acc[2 * d + p], e0[d], e1[d]);
        const int ia = i0 + 4 * iq4 + 2 * p;     // i for e0; ia+1 for e1
        if (ia < INN) {
            __half2 h[4];
            #pragma unroll
            for (int d2 = 0; d2 < 4; d2++)
                h[d2] = __floats2half2_rn(e0[2 * d2], e0[2 * d2 + 1]);
            *reinterpret_cast<uint4*>(g_z + (size_t)ia * NC + n * 32 + 8 * dg) =
                *reinterpret_cast<const uint4*>(h);
        }
        if (ia + 1 < INN) {
            __half2 h[4];
            #pragma unroll
            for (int d2 = 0; d2 < 4; d2++)
                h[d2] = __floats2half2_rn(e1[2 * d2], e1[2 * d2 + 1]);
            *reinterpret_cast<uint4*>(g_z + (size_t)(ia + 1) * NC + n * 32 + 8 * dg) =
                *reinterpret_cast<const uint4*>(h);
        }
    }
}

// ---------------------------------------------------------------------------
// Kernel 2: gather + bias -> y. Block = 8 o, 256 threads.
// Phase A: warp per o, lane = 8 features (16B LDG.128, MLP=16), fp32 acc.
// Phase B: each thread 8 outputs: d = dg*8 + j (full d coverage). Lanes
//          0..7 = o -> 32B contiguous stores.
// ---------------------------------------------------------------------------
__global__ __launch_bounds__(256) void gather_y_kernel(
    const int*   __restrict__ A,      // [OUTN][MAXD]
    const float* __restrict__ mask,   // [OUTN][MAXD]
    const float* __restrict__ bias,   // [OUTC][OUTN]
    float*       __restrict__ y)      // [NBATCH][OUTC][OUTN]
{
    __shared__ float s_y[8][264];     // pad 264: float4-aligned slots
    __shared__ int   s_idx[8 * MAXD];
    __shared__ float s_msk[8 * MAXD];

    const int tid    = threadIdx.x;
    const int o_base = blockIdx.x * 8;

    if (tid < 8 * MAXD) {
        s_idx[tid] = A[(size_t)o_base * MAXD + tid];
        s_msk[tid] = mask[(size_t)o_base * MAXD + tid];
    }
    __syncthreads();

    // ---- Phase A: pooled-z = y minus bias ----
    {
        const int lane = tid & 31;    // features [8*lane, 8*lane+8)
        const int ol   = tid >> 5;    // warp = o within tile

        float2 acc[4];
        #pragma unroll
        for (int j = 0; j < 4; j++) acc[j] = make_float2(0.f, 0.f);

        #pragma unroll
        for (int d = 0; d < MAXD; d++) {
            const int   idx = s_idx[ol * MAXD + d];
            const float m   = s_msk[ol * MAXD + d];
            const uint4 raw = *reinterpret_cast<const uint4*>(
                g_z + (size_t)idx * NC + lane * 8);
            const __half2* h = reinterpret_cast<const __half2*>(&raw);
            #pragma unroll
            for (int j = 0; j < 4; j++) {
                const float2 f = __half22float2(h[j]);
                acc[j].x += m * f.x;
                acc[j].y += m * f.y;
            }
        }
        *reinterpret_cast<float4*>(&s_y[ol][lane * 8]) =
            make_float4(acc[0].x, acc[0].y, acc[1].x, acc[1].y);
        *reinterpret_cast<float4*>(&s_y[ol][lane * 8 + 4]) =
            make_float4(acc[2].x, acc[2].y, acc[3].x, acc[3].y);
    }
    __syncthreads();

    // ---- Phase B: bias + coalesced store (8 values/thread, full d range) ----
    {
        const int ol = tid & 7;           // o within tile (lane-fast -> coalesced)
        const int nn = (tid >> 3) & 7;    // batch
        const int dg = tid >> 6;          // 0..3 -> 8 d each
        const int o  = o_base + ol;
        #pragma unroll
        for (int j = 0; j < 8; j++) {
            const int d = dg * 8 + j;     // covers 0..31
            y[(size_t)nn * (OUTC * OUTN) + (size_t)d * OUTN + o] =
                s_y[ol][nn * 32 + d] + bias[(size_t)d * OUTN + o];
        }
    }
}

// ---------------------------------------------------------------------------
// Launch
// ---------------------------------------------------------------------------
extern "C" void kernel_launch(void* const* d_in, const int* in_sizes, int n_in,
                              void* d_out, int out_size) {
    const float* x      = (const float*)d_in[0];
    const int*   A      = (const int*)  d_in[1];
    const float* mask   = (const float*)d_in[2];
    const float* weight = (const float*)d_in[3];
    const float* bias   = (const float*)d_in[4];
    float*       y      = (float*)d_out;

    {
        dim3 grid((INN + TI - 1) / TI, NBATCH);    // 196 x 8
        xform_kernel<<<grid, 256>>>(x, weight);
    }
    {
        dim3 grid(OUTN / 8);                        // 1024
        gather_y_kernel<<<grid, 256>>>(A, mask, bias, y);
    }
}